// round 2
// baseline (speedup 1.0000x reference)
#include <cuda_runtime.h>
#include <cuda_fp16.h>
#include <cstdint>

#define UNITS   128
#define GATES   512
#define IN_DIM  512
#define BATCH   128
#define SEQ     1024

// scratch (no allocation allowed -> device globals)
__device__ float  g_xw[(size_t)SEQ * BATCH * GATES];   // [t][b][gate]
__device__ __half g_WTh[(size_t)GATES * IN_DIM];       // W^T: [j][i]
__device__ __half g_Uh[(size_t)UNITS * GATES];         // U:   [k][j]

__global__ void conv_w(const float* __restrict__ W) {
    int idx = blockIdx.x * 256 + threadIdx.x;          // 512*512
    int j = idx >> 9, i = idx & 511;
    g_WTh[idx] = __float2half(W[(size_t)i * GATES + j]);
}
__global__ void conv_u(const float* __restrict__ U) {
    int idx = blockIdx.x * 256 + threadIdx.x;          // 128*512
    g_Uh[idx] = __float2half(U[idx]);
}

// ---------------- Phase A: xW GEMM --------------------------------------
#define BM 128
#define BN 128
#define BK 32
#define LDA 40

__global__ __launch_bounds__(256) void gemm_xw(const float* __restrict__ x,
                                               const float* __restrict__ bias) {
    __shared__ __align__(16) __half As[2][BM][LDA];
    __shared__ __align__(16) __half Bs[2][BN][LDA];

    const int tid = threadIdx.x;
    const int nb  = blockIdx.x;      // 0..3  gate-column block
    const int t   = blockIdx.y;      // 0..1023 timestep
    const int lane = tid & 31, wid = tid >> 5;
    const int wm = wid & 3, wn = wid >> 2;     // 4(m) x 2(n) warps
    const int g  = lane >> 2, tg2 = (lane & 3) * 2;

    float acc[2][8][4];
    #pragma unroll
    for (int a = 0; a < 2; a++)
        #pragma unroll
        for (int q = 0; q < 8; q++)
            #pragma unroll
            for (int c = 0; c < 4; c++) acc[a][q][c] = 0.f;

    const int ar = tid >> 3;               // A row (batch) 0..31 (+32*i)
    const int ak = (tid & 7) * 4;          // A k offset
    const float* aptr = x + ((size_t)ar * SEQ + t) * IN_DIM + ak;
    const int bn_ = tid >> 1;              // B row (gate col)
    const int bk_ = (tid & 1) * 16;        // B k offset (halfs)
    const __half* bptr = g_WTh + (size_t)(nb * BN + bn_) * IN_DIM + bk_;

    float4 av[4];
    uint4  bv[2];

    auto ldg = [&](int kt) {
        const float* ap = aptr + kt * BK;
        #pragma unroll
        for (int i = 0; i < 4; i++)
            av[i] = *(const float4*)(ap + (size_t)i * 32 * SEQ * IN_DIM);
        const __half* bp = bptr + kt * BK;
        bv[0] = *(const uint4*)(bp);
        bv[1] = *(const uint4*)(bp + 8);
    };
    auto sts = [&](int buf) {
        #pragma unroll
        for (int i = 0; i < 4; i++) {
            __half2 h0 = __floats2half2_rn(av[i].x, av[i].y);
            __half2 h1 = __floats2half2_rn(av[i].z, av[i].w);
            uint2 u;
            u.x = *reinterpret_cast<unsigned*>(&h0);
            u.y = *reinterpret_cast<unsigned*>(&h1);
            *(uint2*)&As[buf][ar + 32 * i][ak] = u;
        }
        *(uint4*)&Bs[buf][bn_][bk_]     = bv[0];
        *(uint4*)&Bs[buf][bn_][bk_ + 8] = bv[1];
    };

    ldg(0); sts(0); __syncthreads();

    #pragma unroll 1
    for (int kt = 0; kt < 16; kt++) {
        const int cur = kt & 1;
        if (kt < 15) ldg(kt + 1);

        #pragma unroll
        for (int ks = 0; ks < 2; ks++) {
            const int k0 = ks * 16;
            uint32_t afr[2][4], bfr[8][2];
            #pragma unroll
            for (int mt = 0; mt < 2; mt++) {
                const int m0 = wm * 32 + mt * 16;
                afr[mt][0] = *(const uint32_t*)&As[cur][m0 + g    ][k0 + tg2    ];
                afr[mt][1] = *(const uint32_t*)&As[cur][m0 + g + 8][k0 + tg2    ];
                afr[mt][2] = *(const uint32_t*)&As[cur][m0 + g    ][k0 + tg2 + 8];
                afr[mt][3] = *(const uint32_t*)&As[cur][m0 + g + 8][k0 + tg2 + 8];
            }
            #pragma unroll
            for (int nt = 0; nt < 8; nt++) {
                const int n0 = wn * 64 + nt * 8 + g;
                bfr[nt][0] = *(const uint32_t*)&Bs[cur][n0][k0 + tg2    ];
                bfr[nt][1] = *(const uint32_t*)&Bs[cur][n0][k0 + tg2 + 8];
            }
            #pragma unroll
            for (int mt = 0; mt < 2; mt++)
                #pragma unroll
                for (int nt = 0; nt < 8; nt++) {
                    float* c = acc[mt][nt];
                    asm volatile(
                        "mma.sync.aligned.m16n8k16.row.col.f32.f16.f16.f32 "
                        "{%0,%1,%2,%3}, {%4,%5,%6,%7}, {%8,%9}, {%0,%1,%2,%3};\n"
                        : "+f"(c[0]), "+f"(c[1]), "+f"(c[2]), "+f"(c[3])
                        : "r"(afr[mt][0]), "r"(afr[mt][1]), "r"(afr[mt][2]), "r"(afr[mt][3]),
                          "r"(bfr[nt][0]), "r"(bfr[nt][1]));
                }
        }
        if (kt < 15) { sts(1 - cur); __syncthreads(); }
    }

    #pragma unroll
    for (int mt = 0; mt < 2; mt++) {
        const int r0 = wm * 32 + mt * 16 + g;
        #pragma unroll
        for (int nt = 0; nt < 8; nt++) {
            const int col = nb * BN + wn * 64 + nt * 8 + tg2;
            const float b0 = __ldg(&bias[col]), b1 = __ldg(&bias[col + 1]);
            float2 v0 = make_float2(acc[mt][nt][0] + b0, acc[mt][nt][1] + b1);
            float2 v1 = make_float2(acc[mt][nt][2] + b0, acc[mt][nt][3] + b1);
            *(float2*)&g_xw[((size_t)t * BATCH + r0    ) * GATES + col] = v0;
            *(float2*)&g_xw[((size_t)t * BATCH + r0 + 8) * GATES + col] = v1;
        }
    }
}

// ---------------- Phase B: recurrence, 1 CTA per batch element -----------
#define REC_SMEM (131072 + 512 + 2048)

__global__ __launch_bounds__(256) void lstm_rec(float* __restrict__ out) {
    extern __shared__ __align__(16) char smem[];
    __half2* Us2  = (__half2*)smem;                 // U[k][2t..2t+1], idx k*256+t
    __half2* hh   = (__half2*)(smem + 131072);      // (h_k, h_k) pairs
    float*   zbuf = (float*)(smem + 131072 + 512);

    const int b = blockIdx.x;
    const int t = threadIdx.x;      // owns gate cols 2t, 2t+1

    {   // load U fp16 -> smem (128 KB)
        const uint4* src = (const uint4*)g_Uh;
        uint4* dst = (uint4*)smem;
        #pragma unroll
        for (int i = 0; i < 32; i++) dst[t + 256 * i] = src[t + 256 * i];
    }
    if (t < UNITS) hh[t] = __float2half2_rn(0.f);
    float c = 0.f, hlast = 0.f;
    __syncthreads();

    const float* xwp = g_xw + (size_t)b * GATES + 2 * t;
    const __half2 h2z = __float2half2_rn(0.f);

    for (int step = 0; step < SEQ; step++) {
        const float2 xw = *(const float2*)xwp;   // prefetch, consumed late
        xwp += (size_t)BATCH * GATES;

        float acc0 = 0.f, acc1 = 0.f;
        __half2 hacc = h2z;
        const uint4* hh4 = (const uint4*)hh;
        #pragma unroll
        for (int kb = 0; kb < 32; kb++) {        // fp16 partials, fp32 flush /4k
            union { uint4 v; __half2 h[4]; } hu;
            hu.v = hh4[kb];                      // broadcast LDS.128
            #pragma unroll
            for (int j = 0; j < 4; j++) {
                __half2 u = Us2[(kb * 4 + j) * 256 + t];
                hacc = __hfma2(hu.h[j], u, hacc);
            }
            acc0 += __low2float(hacc);
            acc1 += __high2float(hacc);
            hacc = h2z;
        }
        const float z0 = acc0 + xw.x;
        const float z1 = acc1 + xw.y;
        *(float2*)&zbuf[2 * t] = make_float2(tanhf(z0), tanhf(z1));
        __syncthreads();

        if (t < UNITS) {
            const float i_ = zbuf[t];
            const float f_ = zbuf[t + 128];
            const float g_ = zbuf[t + 256];
            const float o_ = zbuf[t + 384];
            c = f_ * c + i_ * g_;
            hlast = o_ * tanhf(c);
            hh[t] = __floats2half2_rn(hlast, hlast);
        }
        __syncthreads();
    }
    if (t < UNITS) out[(size_t)b * UNITS + t] = hlast;
}

// ---------------- launch -------------------------------------------------
extern "C" void kernel_launch(void* const* d_in, const int* in_sizes, int n_in,
                              void* d_out, int out_size) {
    const float* x = (const float*)d_in[0];
    const float* W = (const float*)d_in[1];
    const float* U = (const float*)d_in[2];
    const float* b = (const float*)d_in[3];
    float* out = (float*)d_out;

    cudaFuncSetAttribute(lstm_rec, cudaFuncAttributeMaxDynamicSharedMemorySize, REC_SMEM);

    conv_w<<<(GATES * IN_DIM) / 256, 256>>>(W);
    conv_u<<<(UNITS * GATES) / 256, 256>>>(U);
    gemm_xw<<<dim3(4, SEQ), 256>>>(x, b);
    lstm_rec<<<BATCH, 256, REC_SMEM>>>(out);
}